// round 15
// baseline (speedup 1.0000x reference)
#include <cuda_runtime.h>
#include <cstdint>

// Problem constants (fixed by the reference: B=16, L=4096, D=512, WORD_SIZE=128, WORD_LEN=2)
#define NWORDS 32768     // B * (L/2)
#define DIM    512
#define NC     128       // codebook rows
#define BM     128       // words per CTA tile
#define BK     16        // k-chunk (R12-proven)
#define BMP    (BM + 4)  // A smem pitch
#define NCP2   148       // B smem pitch: gap-padded, conflict-free LDS.128 loads
#define NCHUNK (DIM / BK)      // 32
#define GRID   (NWORDS / BM)   // 256 CTAs
#define NT     512             // threads per CTA
#define NDG    64              // d-groups for prep partials

// Scratch (no allocations allowed -> __device__ globals)
__device__ float    g_cbT[DIM * NC];     // transposed codebook: cbT[k][c]
__device__ float    g_cnorm[NC];         // ||C_c||^2 (fixed-order, R6-validated path)
__device__ float    g_s_part[NDG][NC];   // partial ||P-C||^2 per (d-group, code)
__device__ int      g_count[NC];         // histogram of argmin indices
__device__ unsigned g_done;              // last-CTA election (zero-init; reset by last CTA)

// ---- packed f32x2 helpers (each half = independent IEEE fp32 op) -----------
__device__ __forceinline__ unsigned long long dup2(float x) {
    unsigned long long r;
    asm("mov.b64 %0, {%1, %1};" : "=l"(r) : "f"(x));
    return r;
}
__device__ __forceinline__ void ffma2(unsigned long long& d,
                                      unsigned long long a,
                                      unsigned long long b) {
    asm("fma.rn.f32x2 %0, %1, %2, %0;" : "+l"(d) : "l"(a), "l"(b));
}
__device__ __forceinline__ float2 unpack2(unsigned long long v) {
    float2 f;
    asm("mov.b64 {%0, %1}, %2;" : "=f"(f.x), "=f"(f.y) : "l"(v));
    return f;
}

// Overlay: GEMM tile buffers (main loop) vs epilogue arrays (after loop).
struct MainBufs {
    float m[2][BK][BMP];    // 16.9 KB
    float c[2][BK][NCP2];   // 18.9 KB
};
struct EpiBufs {
    float fold[BM][17];     // mnorm chains
    float bs[BM][17];       // per-(word, co-group) best score
    int   bi[BM][17];       // and best index
};
union SmemU { MainBufs mb; EpiBufs eb; };
#define DSMEM ((int)sizeof(SmemU))      // ~35.8 KB dynamic

// ---------------------------------------------------------------------------
// Kernel 0: transpose codebook (cbT[k][c] = cb[c][k]) + cnorm[c] (fixed-order
// fold; deterministic-global-cnorm class validated rel_err==0.0 in R6/R7).
// ---------------------------------------------------------------------------
__global__ __launch_bounds__(256)
void transpose_kernel(const float* __restrict__ cb) {
    const int c = blockIdx.x;      // code row
    const int t = threadIdx.x;     // 256
    __shared__ float wsum[8];

    const float v0 = __ldg(&cb[(size_t)c * DIM + t]);
    const float v1 = __ldg(&cb[(size_t)c * DIM + t + 256]);
    g_cbT[(size_t)t * NC + c]         = v0;
    g_cbT[(size_t)(t + 256) * NC + c] = v1;

    float n = __fmaf_rn(v0, v0, __fmul_rn(v1, v1));
    #pragma unroll
    for (int o = 16; o; o >>= 1) n += __shfl_down_sync(0xffffffffu, n, o);
    if ((t & 31) == 0) wsum[t >> 5] = n;
    __syncthreads();
    if (t == 0) {
        float s = wsum[0];
        #pragma unroll
        for (int i = 1; i < 8; i++) s = __fadd_rn(s, wsum[i]);
        g_cnorm[c] = s;
    }
}

// ---------------------------------------------------------------------------
// Kernel 1 (512 threads, 4 words x 8 codes per thread, 32 warps/SM target):
//   coalesced prep-slice -> pair-sum + mnorm(LLVM order)
//   -> fp32 GEMM (f32x2, double-buffered BK=16; A via LDG+STS one word/thread,
//      B via cp.async from cbT; R12 pipeline order)
//   -> d2 chain -> smem argmin -> histogram -> gather -> last-CTA loss.
//
// Bit-exactness invariants (verified across R7-R14, preserved):
//  * per-(word,code) dot: single fp32 accumulator, FMA over ascending k.
//  * mnorm: 16 chains per word, part_p[l] = sum_i y[16i+4p+l], i = chunk
//    ascending; thread lq == p, components l = 0..3; fold ((P0+P1)+P2)+P3
//    then (v0+v1)+(v2+v3); y = fl(m^2), m = fl(fl(a+b)*0.5).
//  * d2 = fl(fl(mnorm - acc) + cnorm); argmin first-min (lowest index).
//  * cnorm/loss: fixed fold order (order noise ~1e-9 << 3e-5 d2 granularity).
// ---------------------------------------------------------------------------
__global__ __launch_bounds__(NT, 2)
void main_kernel(const float* __restrict__ emb,   // [NWORDS*2, DIM]
                 const float* __restrict__ cb,    // [NC, DIM]
                 const float* __restrict__ W,     // [DIM, DIM]
                 const float* __restrict__ bias,  // [DIM]
                 float* __restrict__ out_idx,     // NWORDS floats
                 float* __restrict__ out_emb,     // NWORDS*DIM floats
                 float* __restrict__ out_loss) {  // 1 float
    extern __shared__ __align__(16) char dsm[];
    SmemU& u = *reinterpret_cast<SmemU*>(dsm);

    __shared__ float sm_mn[BM];
    __shared__ float sm_ls[4];
    __shared__ int   widx[BM];
    __shared__ int   hist[NC];
    __shared__ int   is_last;

    const int t = threadIdx.x;
    const int bid = blockIdx.x;
    const int wbase = bid * BM;

    if (t < NC) hist[t] = 0;

    // compute-map: warp tile = 16 words x 64 codes
    const int w  = t >> 5, l = t & 31;
    const int wo = ((w >> 1) << 2) + (l >> 3);   // 0..31 word group (4 words)
    const int co = ((w & 1) << 3) + (l & 7);     // 0..15 code group (8 codes)
    // loader-map (fixed: mnorm chain identity depends on it): one word/thread
    const int lw = t >> 2;   // 0..127 word
    const int lq = t & 3;    // 0..3  (== mnorm part index p)

    unsigned long long acc2[4][4];      // 4 words x 4 code-pairs
    #pragma unroll
    for (int i = 0; i < 4; i++)
        #pragma unroll
        for (int jp = 0; jp < 4; jp++) acc2[i][jp] = 0ull;

    float4 macc = make_float4(0.f, 0.f, 0.f, 0.f);   // mnorm chains (p=lq, word lw)
    float4 pa0, pa1;                                 // A prefetch: char rows 2w, 2w+1

    auto do_ldg = [&](int c) {
        const int kc = c * BK;
        const size_t r0 = (size_t)(wbase + lw) * 2 * DIM + kc + lq * 4;
        pa0 = *(const float4*)(emb + r0);
        pa1 = *(const float4*)(emb + r0 + DIM);
    };

    auto do_store = [&](int buf) {
        float (*mm)[BMP] = u.mb.m[buf];
        float s0 = __fadd_rn(pa0.x, pa1.x);
        float s1 = __fadd_rn(pa0.y, pa1.y);
        float s2 = __fadd_rn(pa0.z, pa1.z);
        float s3 = __fadd_rn(pa0.w, pa1.w);
        mm[lq * 4 + 0][lw] = s0;
        mm[lq * 4 + 1][lw] = s1;
        mm[lq * 4 + 2][lw] = s2;
        mm[lq * 4 + 3][lw] = s3;
        float m0 = __fmul_rn(s0, 0.5f), m1 = __fmul_rn(s1, 0.5f);
        float m2 = __fmul_rn(s2, 0.5f), m3 = __fmul_rn(s3, 0.5f);
        macc.x = __fadd_rn(macc.x, __fmul_rn(m0, m0));
        macc.y = __fadd_rn(macc.y, __fmul_rn(m1, m1));
        macc.z = __fadd_rn(macc.z, __fmul_rn(m2, m2));
        macc.w = __fadd_rn(macc.w, __fmul_rn(m3, m3));
    };

    // B-tile prefetch via cp.async: chunk c = cbT rows [16c, 16c+16).
    // 512 16B-copies per chunk -> exactly 1 per thread.
    auto cp_b = [&](int c) {
        const int row = t >> 5;          // k within chunk (0..15)
        const int grp = t & 31;          // 4-code group
        const float* src = g_cbT + (size_t)(c * BK + row) * NC + grp * 4;
        uint32_t dst = (uint32_t)__cvta_generic_to_shared(
            &u.mb.c[c & 1][row][grp * 4 + ((grp >> 3) << 2)]);
        asm volatile("cp.async.cg.shared.global [%0], [%1], 16;"
                     :: "r"(dst), "l"(src));
        asm volatile("cp.async.commit_group;" ::: "memory");
    };

    const int bcol = co * 8 + ((co >> 2) << 2);   // gap-padded B base col

    // ---- prologue (R12 order): A0+B0 in flight, prep slice under latency ----
    do_ldg(0);
    cp_b(0);

    // prep slice (COALESCED): CTA (cg = bid&3, dg = bid>>2) computes partial s
    // over d in [dg*8, dg*8+8) for codes [cg*32, cg*32+32).  Loss-only.
    // 16 warps x 2 codes each.
    {
        const int cg = bid & 3, dg = bid >> 2;
        #pragma unroll
        for (int ci = 0; ci < 2; ci++) {
            const int c = cg * 32 + w * 2 + ci;
            const float* crow = cb + (size_t)c * DIM;
            float creg[16];
            #pragma unroll
            for (int j = 0; j < 16; j++) creg[j] = __ldg(&crow[l + 32 * j]);
            float ssum = 0.f;
            #pragma unroll
            for (int dd = 0; dd < 8; dd++) {
                const int d = dg * 8 + dd;
                const float* wrow = W + (size_t)d * DIM;
                float p = 0.f;
                #pragma unroll
                for (int j = 0; j < 16; j++)
                    p = __fmaf_rn(creg[j], __ldg(&wrow[l + 32 * j]), p);
                #pragma unroll
                for (int o = 16; o; o >>= 1)
                    p += __shfl_down_sync(0xffffffffu, p, o);
                if (l == 0) {
                    float diff = p + __ldg(&bias[d]) - __ldg(&crow[d]);
                    ssum = __fadd_rn(ssum, diff * diff);
                }
            }
            if (l == 0) g_s_part[dg][c] = ssum;
        }
    }

    do_store(0);
    do_ldg(1);
    asm volatile("cp.async.wait_group 0;" ::: "memory");
    __syncthreads();

    // ---- pipelined main loop (R12 order): one barrier per chunk ----
    for (int c = 0; c < NCHUNK; c++) {
        if (c + 1 < NCHUNK) {
            do_store((c + 1) & 1);       // ascending chunk order -> chains intact
            cp_b(c + 1);
        }
        if (c + 2 < NCHUNK) do_ldg(c + 2);

        const float (*mm)[BMP]  = u.mb.m[c & 1];
        const float (*cc)[NCP2] = u.mb.c[c & 1];
        #pragma unroll
        for (int k = 0; k < BK; k++) {
            float4 a0 = *(const float4*)&mm[k][wo * 4];
            ulonglong2 q0 = *(const ulonglong2*)&cc[k][bcol];
            ulonglong2 q1 = *(const ulonglong2*)&cc[k][bcol + 4];
            const unsigned long long bp0 = q0.x, bp1 = q0.y, bp2 = q1.x, bp3 = q1.y;
            const float av[4] = {a0.x, a0.y, a0.z, a0.w};
            #pragma unroll
            for (int i = 0; i < 4; i++) {
                const unsigned long long aa = dup2(av[i]);
                ffma2(acc2[i][0], aa, bp0);
                ffma2(acc2[i][1], aa, bp1);
                ffma2(acc2[i][2], aa, bp2);
                ffma2(acc2[i][3], aa, bp3);
            }
        }
        if (c + 1 < NCHUNK) {
            asm volatile("cp.async.wait_group 0;" ::: "memory");
            __syncthreads();
        }
    }
    __syncthreads();   // all warps done reading tile buffers before epilogue overlay

    // ---- mnorm fold (LLVM order); u.eb.fold aliases the dead tile buffers ----
    u.eb.fold[lw][lq * 4 + 0] = macc.x;
    u.eb.fold[lw][lq * 4 + 1] = macc.y;
    u.eb.fold[lw][lq * 4 + 2] = macc.z;
    u.eb.fold[lw][lq * 4 + 3] = macc.w;
    __syncthreads();
    if (t < BM) {
        const float* s = u.eb.fold[t];
        float v0 = __fadd_rn(__fadd_rn(__fadd_rn(s[0], s[4]), s[8]),  s[12]);
        float v1 = __fadd_rn(__fadd_rn(__fadd_rn(s[1], s[5]), s[9]),  s[13]);
        float v2 = __fadd_rn(__fadd_rn(__fadd_rn(s[2], s[6]), s[10]), s[14]);
        float v3 = __fadd_rn(__fadd_rn(__fadd_rn(s[3], s[7]), s[11]), s[15]);
        sm_mn[t] = __fadd_rn(__fadd_rn(v0, v1), __fadd_rn(v2, v3));
    }
    __syncthreads();

    // ---- unpack + per-thread argmin, results to smem ----
    float cn[8];
    #pragma unroll
    for (int j = 0; j < 8; j++) cn[j] = __ldg(&g_cnorm[co * 8 + j]);

    #pragma unroll
    for (int i = 0; i < 4; i++) {
        float a[8];
        #pragma unroll
        for (int jp = 0; jp < 4; jp++) {
            float2 v = unpack2(acc2[i][jp]);
            a[2 * jp] = v.x; a[2 * jp + 1] = v.y;
        }
        const float mni = sm_mn[wo * 4 + i];
        float best;
        int bidx = co * 8;
        {
            float tt = __fadd_rn(mni, -a[0]);
            best = __fadd_rn(tt, cn[0]);
        }
        #pragma unroll
        for (int j = 1; j < 8; j++) {
            float tt = __fadd_rn(mni, -a[j]);
            float d2 = __fadd_rn(tt, cn[j]);
            if (d2 < best) { best = d2; bidx = co * 8 + j; }  // strict <: lowest j
        }
        u.eb.bs[wo * 4 + i][co] = best;
        u.eb.bi[wo * 4 + i][co] = bidx;
    }
    __syncthreads();

    // ---- per-word reduction over the 16 co-groups, ascending (first-min) ----
    if (t < BM) {
        float best = u.eb.bs[t][0];
        int   bidx = u.eb.bi[t][0];
        #pragma unroll
        for (int g = 1; g < 16; g++) {
            float s = u.eb.bs[t][g];
            if (s < best) { best = s; bidx = u.eb.bi[t][g]; } // strict <: lowest co
        }
        widx[t] = bidx;
        out_idx[wbase + t] = (float)bidx;
        atomicAdd(&hist[bidx], 1);
    }
    __syncthreads();

    if (t < NC) {
        int h = hist[t];
        if (h) atomicAdd(&g_count[t], h);
    }

    // ---- gather-write word_embeddings (codebook L2-hot, coalesced stores) ----
    for (int f = t; f < BM * (DIM / 4); f += NT) {
        const int wd = f >> 7;
        const int c4 = f & 127;
        const int c  = widx[wd];
        float4 v = *(const float4*)(cb + (size_t)c * DIM + c4 * 4);
        *(float4*)(out_emb + (size_t)(wbase + wd) * DIM + c4 * 4) = v;
    }

    // ---- last-CTA loss: sum_c count[c] * (sum_dg s_part[dg][c]) / (NWORDS*DIM) ----
    __syncthreads();
    if (t == 0) {
        __threadfence();
        unsigned old = atomicAdd(&g_done, 1u);
        is_last = (old == gridDim.x - 1) ? 1 : 0;
    }
    __syncthreads();
    if (is_last) {
        float v = 0.f;
        if (t < NC) {
            __threadfence();
            float s = 0.f;
            #pragma unroll 8
            for (int p = 0; p < NDG; p++)
                s = __fadd_rn(s, g_s_part[p][t]);   // fixed ascending order
            const int cnt = *(volatile int*)&g_count[t];
            v = __fmul_rn((float)cnt, s);
            g_count[t] = 0;                          // reset for next replay
        }
        if (t < BM) {
            #pragma unroll
            for (int o = 16; o; o >>= 1) v += __shfl_down_sync(0xffffffffu, v, o);
            if ((t & 31) == 0) sm_ls[t >> 5] = v;
        }
        __syncthreads();
        if (t == 0) {
            float s = __fadd_rn(__fadd_rn(sm_ls[0], sm_ls[1]),
                                __fadd_rn(sm_ls[2], sm_ls[3]));
            out_loss[0] = s * (1.0f / ((float)NWORDS * (float)DIM));
            g_done = 0;
        }
    }
}

// ---------------------------------------------------------------------------
// Inputs (metadata order):
//   d_in[0] char_tokens int32 (unused)  d_in[1] char_embeddings f32 [16,4096,512]
//   d_in[2] word_codebook f32 [128,512] d_in[3] proj_w f32 [512,512]
//   d_in[4] proj_b f32 [512]
// Output (f32, flattened): [0,32768) indices | [.., +32768*512) embeddings | [last] loss
// ---------------------------------------------------------------------------
extern "C" void kernel_launch(void* const* d_in, const int* in_sizes, int n_in,
                              void* d_out, int out_size) {
    const float* emb = (const float*)d_in[1];
    const float* cb  = (const float*)d_in[2];
    const float* W   = (const float*)d_in[3];
    const float* b   = (const float*)d_in[4];
    float* out = (float*)d_out;

    float* out_idx  = out;
    float* out_emb  = out + NWORDS;
    float* out_loss = out + NWORDS + (size_t)NWORDS * DIM;

    cudaFuncSetAttribute(main_kernel,
                         cudaFuncAttributeMaxDynamicSharedMemorySize, DSMEM);

    transpose_kernel<<<NC, 256>>>(cb);
    main_kernel<<<GRID, NT, DSMEM>>>(emb, cb, W, b, out_idx, out_emb, out_loss);
}

// round 16
// speedup vs baseline: 1.0376x; 1.0376x over previous
#include <cuda_runtime.h>
#include <cstdint>

// Problem constants (fixed by the reference: B=16, L=4096, D=512, WORD_SIZE=128, WORD_LEN=2)
#define NWORDS 32768     // B * (L/2)
#define DIM    512
#define NC     128       // codebook rows
#define BM     128       // words per CTA tile
#define BK     16        // k-chunk (R12-proven)
#define BMP    (BM + 4)  // A smem pitch
#define NCP2   148       // B smem pitch: gap-padded, conflict-free LDS.128 loads
#define NCHUNK (DIM / BK)      // 32
#define GRID   (NWORDS / BM)   // 256 CTAs
#define NDG    64              // d-groups for prep partials

// Scratch (no allocations allowed -> __device__ globals)
__device__ float    g_cbT[DIM * NC];     // transposed codebook: cbT[k][c]
__device__ float    g_cnorm[NC];         // ||C_c||^2 (fixed-order, R6-validated path)
__device__ float    g_s_part[NDG][NC];   // partial ||P-C||^2 per (d-group, code)
__device__ int      g_count[NC];         // histogram of argmin indices
__device__ unsigned g_done;              // last-CTA election (zero-init; reset by last CTA)

// ---- packed f32x2 helpers (each half = independent IEEE fp32 op) -----------
__device__ __forceinline__ unsigned long long dup2(float x) {
    unsigned long long r;
    asm("mov.b64 %0, {%1, %1};" : "=l"(r) : "f"(x));
    return r;
}
__device__ __forceinline__ void ffma2(unsigned long long& d,
                                      unsigned long long a,
                                      unsigned long long b) {
    asm("fma.rn.f32x2 %0, %1, %2, %0;" : "+l"(d) : "l"(a), "l"(b));
}
__device__ __forceinline__ float2 unpack2(unsigned long long v) {
    float2 f;
    asm("mov.b64 {%0, %1}, %2;" : "=f"(f.x), "=f"(f.y) : "l"(v));
    return f;
}

// Overlay: GEMM tile buffers (main loop) vs epilogue arrays (after loop).
// B is TRIPLE-buffered: cp.async issued 2 chunks ahead, wait_group 1 at the
// chunk boundary only requires the NEXT chunk's copy (issued a full chunk
// earlier) to have landed.
struct MainBufs {
    float m[2][BK][BMP];    // 16.9 KB  (A double-buffered, register-prefetched)
    float c[3][BK][NCP2];   // 28.4 KB  (B triple-buffered via cp.async)
};
struct EpiBufs {
    float fold[BM][17];     // mnorm chains
    float bs[BM][17];       // per-(word, co-group) best score
    int   bi[BM][17];       // and best index
};
union SmemU { MainBufs mb; EpiBufs eb; };
#define DSMEM ((int)sizeof(SmemU))      // ~45.3 KB dynamic

// ---------------------------------------------------------------------------
// Kernel 0: transpose codebook (cbT[k][c] = cb[c][k]) + cnorm[c] (fixed-order
// fold; deterministic-global-cnorm class validated rel_err==0.0 in R6/R7).
// ---------------------------------------------------------------------------
__global__ __launch_bounds__(256)
void transpose_kernel(const float* __restrict__ cb) {
    const int c = blockIdx.x;      // code row
    const int t = threadIdx.x;     // 256
    __shared__ float wsum[8];

    const float v0 = __ldg(&cb[(size_t)c * DIM + t]);
    const float v1 = __ldg(&cb[(size_t)c * DIM + t + 256]);
    g_cbT[(size_t)t * NC + c]         = v0;
    g_cbT[(size_t)(t + 256) * NC + c] = v1;

    float n = __fmaf_rn(v0, v0, __fmul_rn(v1, v1));
    #pragma unroll
    for (int o = 16; o; o >>= 1) n += __shfl_down_sync(0xffffffffu, n, o);
    if ((t & 31) == 0) wsum[t >> 5] = n;
    __syncthreads();
    if (t == 0) {
        float s = wsum[0];
        #pragma unroll
        for (int i = 1; i < 8; i++) s = __fadd_rn(s, wsum[i]);
        g_cnorm[c] = s;
    }
}

// ---------------------------------------------------------------------------
// Kernel 1 (R12 shape: 256 threads, 8 words x 8 codes per thread):
//   coalesced prep-slice -> pair-sum + mnorm(LLVM order)
//   -> fp32 GEMM (f32x2, A double-buffered LDG+STS, B TRIPLE-buffered
//      cp.async depth-2 from cbT; one barrier per chunk)
//   -> d2 chain -> smem argmin -> histogram -> gather -> last-CTA loss.
//
// Bit-exactness invariants (verified across R7-R15, preserved):
//  * per-(word,code) dot: single fp32 accumulator, FMA over ascending k.
//  * mnorm: 16 chains per word, part_p[l] = sum_i y[16i+4p+l], i = chunk
//    ascending (ascending do_store order); loader lq == p, component == l;
//    fold ((P0+P1)+P2)+P3 then (v0+v1)+(v2+v3); y = fl(m^2), m = fl(fl(a+b)*0.5).
//  * d2 = fl(fl(mnorm - acc) + cnorm); argmin first-min (lowest index).
//  * cnorm/loss: fixed fold order (order noise ~1e-9 << 3e-5 d2 granularity).
// ---------------------------------------------------------------------------
__global__ __launch_bounds__(256, 2)
void main_kernel(const float* __restrict__ emb,   // [NWORDS*2, DIM]
                 const float* __restrict__ cb,    // [NC, DIM]
                 const float* __restrict__ W,     // [DIM, DIM]
                 const float* __restrict__ bias,  // [DIM]
                 float* __restrict__ out_idx,     // NWORDS floats
                 float* __restrict__ out_emb,     // NWORDS*DIM floats
                 float* __restrict__ out_loss) {  // 1 float
    extern __shared__ __align__(16) char dsm[];
    SmemU& u = *reinterpret_cast<SmemU*>(dsm);

    __shared__ float sm_mn[BM];
    __shared__ float sm_ls[8];
    __shared__ int   widx[BM];
    __shared__ int   hist[NC];
    __shared__ int   is_last;

    const int t = threadIdx.x;
    const int bid = blockIdx.x;
    const int wbase = bid * BM;

    if (t < NC) hist[t] = 0;

    // compute-map: warp tile = 32 words x 64 codes (4 wq x 8 cq)
    const int w  = t >> 5, l = t & 31;
    const int wo = ((w >> 1) << 2) + (l >> 3);   // 0..15 word group (8 words)
    const int co = ((w & 1) << 3) + (l & 7);     // 0..15 code group (8 codes)
    // loader-map (fixed: mnorm chain identity depends on it)
    const int lw = t >> 2;   // 0..63
    const int lq = t & 3;    // 0..3  (== mnorm part index p)

    unsigned long long acc2[8][4];
    #pragma unroll
    for (int i = 0; i < 8; i++)
        #pragma unroll
        for (int jp = 0; jp < 4; jp++) acc2[i][jp] = 0ull;

    float4 macc0 = make_float4(0.f, 0.f, 0.f, 0.f);
    float4 macc1 = make_float4(0.f, 0.f, 0.f, 0.f);

    float4 pa00, pa01, pa10, pa11;   // A register prefetch

    auto do_ldg = [&](int c) {
        const int kc = c * BK;
        const size_t r0 = (size_t)(wbase + lw) * 2 * DIM + kc + lq * 4;
        const size_t r1 = r0 + (size_t)64 * 2 * DIM;
        pa00 = *(const float4*)(emb + r0);
        pa01 = *(const float4*)(emb + r0 + DIM);
        pa10 = *(const float4*)(emb + r1);
        pa11 = *(const float4*)(emb + r1 + DIM);
    };

    auto do_store = [&](int buf) {
        float (*mm)[BMP] = u.mb.m[buf];
        float s0 = __fadd_rn(pa00.x, pa01.x);
        float s1 = __fadd_rn(pa00.y, pa01.y);
        float s2 = __fadd_rn(pa00.z, pa01.z);
        float s3 = __fadd_rn(pa00.w, pa01.w);
        mm[lq * 4 + 0][lw] = s0;
        mm[lq * 4 + 1][lw] = s1;
        mm[lq * 4 + 2][lw] = s2;
        mm[lq * 4 + 3][lw] = s3;
        float m0 = __fmul_rn(s0, 0.5f), m1 = __fmul_rn(s1, 0.5f);
        float m2 = __fmul_rn(s2, 0.5f), m3 = __fmul_rn(s3, 0.5f);
        macc0.x = __fadd_rn(macc0.x, __fmul_rn(m0, m0));
        macc0.y = __fadd_rn(macc0.y, __fmul_rn(m1, m1));
        macc0.z = __fadd_rn(macc0.z, __fmul_rn(m2, m2));
        macc0.w = __fadd_rn(macc0.w, __fmul_rn(m3, m3));

        s0 = __fadd_rn(pa10.x, pa11.x);
        s1 = __fadd_rn(pa10.y, pa11.y);
        s2 = __fadd_rn(pa10.z, pa11.z);
        s3 = __fadd_rn(pa10.w, pa11.w);
        mm[lq * 4 + 0][64 + lw] = s0;
        mm[lq * 4 + 1][64 + lw] = s1;
        mm[lq * 4 + 2][64 + lw] = s2;
        mm[lq * 4 + 3][64 + lw] = s3;
        m0 = __fmul_rn(s0, 0.5f); m1 = __fmul_rn(s1, 0.5f);
        m2 = __fmul_rn(s2, 0.5f); m3 = __fmul_rn(s3, 0.5f);
        macc1.x = __fadd_rn(macc1.x, __fmul_rn(m0, m0));
        macc1.y = __fadd_rn(macc1.y, __fmul_rn(m1, m1));
        macc1.z = __fadd_rn(macc1.z, __fmul_rn(m2, m2));
        macc1.w = __fadd_rn(macc1.w, __fmul_rn(m3, m3));
    };

    // B-tile prefetch via cp.async: chunk c -> buffer c % 3.
    // 512 16B-copies per chunk -> 2 per thread, one commit group per chunk.
    auto cp_b = [&](int c) {
        #pragma unroll
        for (int qq = 0; qq < 2; qq++) {
            const int q   = t * 2 + qq;      // 0..511
            const int row = q >> 5;          // k within chunk (0..15)
            const int grp = q & 31;          // 4-code group
            const float* src = g_cbT + (size_t)(c * BK + row) * NC + grp * 4;
            uint32_t dst = (uint32_t)__cvta_generic_to_shared(
                &u.mb.c[c % 3][row][grp * 4 + ((grp >> 3) << 2)]);
            asm volatile("cp.async.cg.shared.global [%0], [%1], 16;"
                         :: "r"(dst), "l"(src));
        }
        asm volatile("cp.async.commit_group;" ::: "memory");
    };

    const int bcol = co * 8 + ((co >> 2) << 2);   // gap-padded B base col

    // ---- prologue: A0 + B0,B1 in flight, prep slice under the latency ----
    do_ldg(0);
    cp_b(0);

    // prep slice (COALESCED): CTA (cg = bid&3, dg = bid>>2) computes partial s
    // over d in [dg*8, dg*8+8) for codes [cg*32, cg*32+32).  Loss-only.
    {
        const int cg = bid & 3, dg = bid >> 2;
        const int wp = w, ln = l;
        #pragma unroll
        for (int ci = 0; ci < 4; ci++) {
            const int c = cg * 32 + wp * 4 + ci;
            const float* crow = cb + (size_t)c * DIM;
            float creg[16];
            #pragma unroll
            for (int j = 0; j < 16; j++) creg[j] = __ldg(&crow[ln + 32 * j]);
            float ssum = 0.f;
            #pragma unroll
            for (int dd = 0; dd < 8; dd++) {
                const int d = dg * 8 + dd;
                const float* wrow = W + (size_t)d * DIM;
                float p = 0.f;
                #pragma unroll
                for (int j = 0; j < 16; j++)
                    p = __fmaf_rn(creg[j], __ldg(&wrow[ln + 32 * j]), p);
                #pragma unroll
                for (int o = 16; o; o >>= 1)
                    p += __shfl_down_sync(0xffffffffu, p, o);
                if (ln == 0) {
                    float diff = p + __ldg(&bias[d]) - __ldg(&crow[d]);
                    ssum = __fadd_rn(ssum, diff * diff);
                }
            }
            if (ln == 0) g_s_part[dg][c] = ssum;
        }
    }

    do_store(0);
    do_ldg(1);
    cp_b(1);
    asm volatile("cp.async.wait_group 1;" ::: "memory");   // B0 landed; B1 may pend
    __syncthreads();

    // ---- pipelined main loop: one barrier per chunk, B prefetched 2 ahead ----
    for (int c = 0; c < NCHUNK; c++) {
        if (c + 1 < NCHUNK) do_store((c + 1) & 1);  // ascending order -> chains intact
        if (c + 2 < NCHUNK) {
            cp_b(c + 2);
            do_ldg(c + 2);
        }

        const float (*mm)[BMP]  = u.mb.m[c & 1];
        const float (*cc)[NCP2] = u.mb.c[c % 3];
        #pragma unroll
        for (int k = 0; k < BK; k++) {
            float4 a0 = *(const float4*)&mm[k][wo * 8];
            float4 a1 = *(const float4*)&mm[k][wo * 8 + 4];
            ulonglong2 q0 = *(const ulonglong2*)&cc[k][bcol];
            ulonglong2 q1 = *(const ulonglong2*)&cc[k][bcol + 4];
            const unsigned long long bp0 = q0.x, bp1 = q0.y, bp2 = q1.x, bp3 = q1.y;
            const float av[8] = {a0.x, a0.y, a0.z, a0.w, a1.x, a1.y, a1.z, a1.w};
            #pragma unroll
            for (int i = 0; i < 8; i++) {
                const unsigned long long aa = dup2(av[i]);
                ffma2(acc2[i][0], aa, bp0);
                ffma2(acc2[i][1], aa, bp1);
                ffma2(acc2[i][2], aa, bp2);
                ffma2(acc2[i][3], aa, bp3);
            }
        }
        if (c + 2 < NCHUNK) {
            // groups pending: c+1, c+2 -> require c+1 landed
            asm volatile("cp.async.wait_group 1;" ::: "memory");
            __syncthreads();
        } else if (c + 1 < NCHUNK) {
            // nothing new issued; require the last group (c+1) landed
            asm volatile("cp.async.wait_group 0;" ::: "memory");
            __syncthreads();
        }
    }
    __syncthreads();   // all warps done reading tile buffers before epilogue overlay

    // ---- mnorm fold (LLVM order); u.eb.fold aliases the dead tile buffers ----
    u.eb.fold[lw][lq * 4 + 0] = macc0.x;
    u.eb.fold[lw][lq * 4 + 1] = macc0.y;
    u.eb.fold[lw][lq * 4 + 2] = macc0.z;
    u.eb.fold[lw][lq * 4 + 3] = macc0.w;
    u.eb.fold[64 + lw][lq * 4 + 0] = macc1.x;
    u.eb.fold[64 + lw][lq * 4 + 1] = macc1.y;
    u.eb.fold[64 + lw][lq * 4 + 2] = macc1.z;
    u.eb.fold[64 + lw][lq * 4 + 3] = macc1.w;
    __syncthreads();
    if (t < BM) {
        const float* s = u.eb.fold[t];
        float v0 = __fadd_rn(__fadd_rn(__fadd_rn(s[0], s[4]), s[8]),  s[12]);
        float v1 = __fadd_rn(__fadd_rn(__fadd_rn(s[1], s[5]), s[9]),  s[13]);
        float v2 = __fadd_rn(__fadd_rn(__fadd_rn(s[2], s[6]), s[10]), s[14]);
        float v3 = __fadd_rn(__fadd_rn(__fadd_rn(s[3], s[7]), s[11]), s[15]);
        sm_mn[t] = __fadd_rn(__fadd_rn(v0, v1), __fadd_rn(v2, v3));
    }
    __syncthreads();

    // ---- unpack + per-thread argmin, results to smem ----
    float cn[8];
    #pragma unroll
    for (int j = 0; j < 8; j++) cn[j] = __ldg(&g_cnorm[co * 8 + j]);

    #pragma unroll
    for (int i = 0; i < 8; i++) {
        float a[8];
        #pragma unroll
        for (int jp = 0; jp < 4; jp++) {
            float2 v = unpack2(acc2[i][jp]);
            a[2 * jp] = v.x; a[2 * jp + 1] = v.y;
        }
        const float mni = sm_mn[wo * 8 + i];
        float best;
        int bidx = co * 8;
        {
            float tt = __fadd_rn(mni, -a[0]);
            best = __fadd_rn(tt, cn[0]);
        }
        #pragma unroll
        for (int j = 1; j < 8; j++) {
            float tt = __fadd_rn(mni, -a[j]);
            float d2 = __fadd_rn(tt, cn[j]);
            if (d2 < best) { best = d2; bidx = co * 8 + j; }  // strict <: lowest j
        }
        u.eb.bs[wo * 8 + i][co] = best;
        u.eb.bi[wo * 8 + i][co] = bidx;
    }
    __syncthreads();

    // ---- per-word reduction over the 16 co-groups, ascending (first-min) ----
    if (t < BM) {
        float best = u.eb.bs[t][0];
        int   bidx = u.eb.bi[t][0];
        #pragma unroll
        for (int g = 1; g < 16; g++) {
            float s = u.eb.bs[t][g];
            if (s < best) { best = s; bidx = u.eb.bi[t][g]; } // strict <: lowest co
        }
        widx[t] = bidx;
        out_idx[wbase + t] = (float)bidx;
        atomicAdd(&hist[bidx], 1);
    }
    __syncthreads();

    if (t < NC) {
        int h = hist[t];
        if (h) atomicAdd(&g_count[t], h);
    }

    // ---- gather-write word_embeddings (codebook L2-hot, coalesced stores) ----
    for (int f = t; f < BM * (DIM / 4); f += 256) {
        const int wd = f >> 7;
        const int c4 = f & 127;
        const int c  = widx[wd];
        float4 v = *(const float4*)(cb + (size_t)c * DIM + c4 * 4);
        *(float4*)(out_emb + (size_t)(wbase + wd) * DIM + c4 * 4) = v;
    }

    // ---- last-CTA loss: sum_c count[c] * (sum_dg s_part[dg][c]) / (NWORDS*DIM) ----
    __syncthreads();
    if (t == 0) {
        __threadfence();
        unsigned old = atomicAdd(&g_done, 1u);
        is_last = (old == gridDim.x - 1) ? 1 : 0;
    }
    __syncthreads();
    if (is_last) {
        float v = 0.f;
        if (t < NC) {
            __threadfence();
            float s = 0.f;
            #pragma unroll 8
            for (int p = 0; p < NDG; p++)
                s = __fadd_rn(s, g_s_part[p][t]);   // fixed ascending order
            const int cnt = *(volatile int*)&g_count[t];
            v = __fmul_rn((float)cnt, s);
            g_count[t] = 0;                          // reset for next replay
        }
        #pragma unroll
        for (int o = 16; o; o >>= 1) v += __shfl_down_sync(0xffffffffu, v, o);
        if ((t & 31) == 0) sm_ls[t >> 5] = v;
        __syncthreads();
        if (t == 0) {
            float s = sm_ls[0];
            #pragma unroll
            for (int i = 1; i < 8; i++) s = __fadd_rn(s, sm_ls[i]);
            out_loss[0] = s * (1.0f / ((float)NWORDS * (float)DIM));
            g_done = 0;
        }
    }
}

// ---------------------------------------------------------------------------
// Inputs (metadata order):
//   d_in[0] char_tokens int32 (unused)  d_in[1] char_embeddings f32 [16,4096,512]
//   d_in[2] word_codebook f32 [128,512] d_in[3] proj_w f32 [512,512]
//   d_in[4] proj_b f32 [512]
// Output (f32, flattened): [0,32768) indices | [.., +32768*512) embeddings | [last] loss
// ---------------------------------------------------------------------------
extern "C" void kernel_launch(void* const* d_in, const int* in_sizes, int n_in,
                              void* d_out, int out_size) {
    const float* emb = (const float*)d_in[1];
    const float* cb  = (const float*)d_in[2];
    const float* W   = (const float*)d_in[3];
    const float* b   = (const float*)d_in[4];
    float* out = (float*)d_out;

    float* out_idx  = out;
    float* out_emb  = out + NWORDS;
    float* out_loss = out + NWORDS + (size_t)NWORDS * DIM;

    cudaFuncSetAttribute(main_kernel,
                         cudaFuncAttributeMaxDynamicSharedMemorySize, DSMEM);

    transpose_kernel<<<NC, 256>>>(cb);
    main_kernel<<<GRID, 256, DSMEM>>>(emb, cb, W, b, out_idx, out_emb, out_loss);
}

// round 17
// speedup vs baseline: 1.1211x; 1.0805x over previous
#include <cuda_runtime.h>
#include <cstdint>

// Problem constants (fixed by the reference: B=16, L=4096, D=512, WORD_SIZE=128, WORD_LEN=2)
#define NWORDS 32768     // B * (L/2)
#define DIM    512
#define NC     128       // codebook rows
#define BM     64        // words per CTA tile (split CTA: 4 warps, 1 per SMSP)
#define BK     16        // k-chunk (R12-proven)
#define BMP    (BM + 4)  // A smem pitch
#define NCP2   148       // B smem pitch: gap-padded, conflict-free LDS.128 loads
#define NCHUNK (DIM / BK)      // 32
#define GRID   (NWORDS / BM)   // 512 CTAs
#define NT     128             // threads per CTA
#define NDG    128             // d-groups for prep partials (4 d-cols each)

// Scratch (no allocations allowed -> __device__ globals)
__device__ float    g_cbT[DIM * NC];     // transposed codebook: cbT[k][c]
__device__ float    g_cnorm[NC];         // ||C_c||^2 (fixed-order, R6-validated path)
__device__ float    g_s_part[NDG][NC];   // partial ||P-C||^2 per (d-group, code)
__device__ int      g_count[NC];         // histogram of argmin indices
__device__ unsigned g_done;              // last-CTA election (zero-init; reset by last CTA)

// ---- packed f32x2 helpers (each half = independent IEEE fp32 op) -----------
__device__ __forceinline__ unsigned long long dup2(float x) {
    unsigned long long r;
    asm("mov.b64 %0, {%1, %1};" : "=l"(r) : "f"(x));
    return r;
}
__device__ __forceinline__ void ffma2(unsigned long long& d,
                                      unsigned long long a,
                                      unsigned long long b) {
    asm("fma.rn.f32x2 %0, %1, %2, %0;" : "+l"(d) : "l"(a), "l"(b));
}
__device__ __forceinline__ float2 unpack2(unsigned long long v) {
    float2 f;
    asm("mov.b64 {%0, %1}, %2;" : "=f"(f.x), "=f"(f.y) : "l"(v));
    return f;
}

// Overlay: GEMM tile buffers (main loop) vs epilogue arrays (after loop).
struct MainBufs {
    float m[2][BK][BMP];    // 8.7 KB  (A double-buffered, register-prefetched)
    float c[2][BK][NCP2];   // 18.9 KB (B double-buffered via cp.async, R12 shape)
};
struct EpiBufs {
    float fold[BM][17];     // mnorm chains
    float bs[BM][17];       // per-(word, co-group) best score
    int   bi[BM][17];       // and best index
};
union SmemU { MainBufs mb; EpiBufs eb; };
#define DSMEM ((int)sizeof(SmemU))      // ~27.6 KB dynamic

// ---------------------------------------------------------------------------
// Kernel 0: transpose codebook (cbT[k][c] = cb[c][k]) + cnorm[c] (fixed-order
// fold; deterministic-global-cnorm class validated rel_err==0.0 in R6/R7).
// ---------------------------------------------------------------------------
__global__ __launch_bounds__(256)
void transpose_kernel(const float* __restrict__ cb) {
    const int c = blockIdx.x;      // code row
    const int t = threadIdx.x;     // 256
    __shared__ float wsum[8];

    const float v0 = __ldg(&cb[(size_t)c * DIM + t]);
    const float v1 = __ldg(&cb[(size_t)c * DIM + t + 256]);
    g_cbT[(size_t)t * NC + c]         = v0;
    g_cbT[(size_t)(t + 256) * NC + c] = v1;

    float n = __fmaf_rn(v0, v0, __fmul_rn(v1, v1));
    #pragma unroll
    for (int o = 16; o; o >>= 1) n += __shfl_down_sync(0xffffffffu, n, o);
    if ((t & 31) == 0) wsum[t >> 5] = n;
    __syncthreads();
    if (t == 0) {
        float s = wsum[0];
        #pragma unroll
        for (int i = 1; i < 8; i++) s = __fadd_rn(s, wsum[i]);
        g_cnorm[c] = s;
    }
}

// ---------------------------------------------------------------------------
// Kernel 1 (128 threads, 4 warps = 1/SMSP, 4 CTAs/SM -> phase-decorrelated):
//   coalesced prep-slice -> pair-sum + mnorm(LLVM order)
//   -> fp32 GEMM (f32x2, A double-buffered LDG+STS, B double-buffered
//      cp.async from cbT; R12 pipeline order, one barrier per chunk)
//   -> d2 chain -> smem argmin -> histogram -> gather -> last-CTA loss.
//
// Bit-exactness invariants (verified across R7-R16, preserved):
//  * per-(word,code) dot: single fp32 accumulator, FMA over ascending k.
//  * mnorm: 16 chains per word, part_p[l] = sum_i y[16i+4p+l], i = chunk
//    ascending (ascending do_store order); loader lq == p, component == l;
//    fold ((P0+P1)+P2)+P3 then (v0+v1)+(v2+v3); y = fl(m^2), m = fl(fl(a+b)*0.5).
//  * d2 = fl(fl(mnorm - acc) + cnorm); argmin first-min (lowest index).
//  * cnorm/loss: fixed fold order (order noise ~1e-9 << 3e-5 d2 granularity).
// ---------------------------------------------------------------------------
__global__ __launch_bounds__(NT, 4)
void main_kernel(const float* __restrict__ emb,   // [NWORDS*2, DIM]
                 const float* __restrict__ cb,    // [NC, DIM]
                 const float* __restrict__ W,     // [DIM, DIM]
                 const float* __restrict__ bias,  // [DIM]
                 float* __restrict__ out_idx,     // NWORDS floats
                 float* __restrict__ out_emb,     // NWORDS*DIM floats
                 float* __restrict__ out_loss) {  // 1 float
    extern __shared__ __align__(16) char dsm[];
    SmemU& u = *reinterpret_cast<SmemU*>(dsm);

    __shared__ float sm_mn[BM];
    __shared__ float sm_ls[4];
    __shared__ int   widx[BM];
    __shared__ int   hist[NC];
    __shared__ int   is_last;

    const int t = threadIdx.x;
    const int bid = blockIdx.x;
    const int wbase = bid * BM;

    if (t < NC) hist[t] = 0;

    // compute-map: warp tile = 32 words x 64 codes (4 wq x 8 cq), same pattern
    // as the proven R12 map (conflict-free B loads), w in 0..3.
    const int w  = t >> 5, l = t & 31;
    const int wo = ((w >> 1) << 2) + (l >> 3);   // 0..7 word group (8 words)
    const int co = ((w & 1) << 3) + (l & 7);     // 0..15 code group (8 codes)
    // loader-map (fixed: mnorm chain identity depends on it)
    const int lw = t >> 2;   // 0..31 (words lw and 32+lw)
    const int lq = t & 3;    // 0..3  (== mnorm part index p)

    unsigned long long acc2[8][4];
    #pragma unroll
    for (int i = 0; i < 8; i++)
        #pragma unroll
        for (int jp = 0; jp < 4; jp++) acc2[i][jp] = 0ull;

    float4 macc0 = make_float4(0.f, 0.f, 0.f, 0.f);   // chains for word lw
    float4 macc1 = make_float4(0.f, 0.f, 0.f, 0.f);   // chains for word 32+lw

    float4 pa00, pa01, pa10, pa11;   // A register prefetch

    auto do_ldg = [&](int c) {
        const int kc = c * BK;
        const size_t r0 = (size_t)(wbase + lw) * 2 * DIM + kc + lq * 4;
        const size_t r1 = r0 + (size_t)32 * 2 * DIM;
        pa00 = *(const float4*)(emb + r0);
        pa01 = *(const float4*)(emb + r0 + DIM);
        pa10 = *(const float4*)(emb + r1);
        pa11 = *(const float4*)(emb + r1 + DIM);
    };

    auto do_store = [&](int buf) {
        float (*mm)[BMP] = u.mb.m[buf];
        float s0 = __fadd_rn(pa00.x, pa01.x);
        float s1 = __fadd_rn(pa00.y, pa01.y);
        float s2 = __fadd_rn(pa00.z, pa01.z);
        float s3 = __fadd_rn(pa00.w, pa01.w);
        mm[lq * 4 + 0][lw] = s0;
        mm[lq * 4 + 1][lw] = s1;
        mm[lq * 4 + 2][lw] = s2;
        mm[lq * 4 + 3][lw] = s3;
        float m0 = __fmul_rn(s0, 0.5f), m1 = __fmul_rn(s1, 0.5f);
        float m2 = __fmul_rn(s2, 0.5f), m3 = __fmul_rn(s3, 0.5f);
        macc0.x = __fadd_rn(macc0.x, __fmul_rn(m0, m0));
        macc0.y = __fadd_rn(macc0.y, __fmul_rn(m1, m1));
        macc0.z = __fadd_rn(macc0.z, __fmul_rn(m2, m2));
        macc0.w = __fadd_rn(macc0.w, __fmul_rn(m3, m3));

        s0 = __fadd_rn(pa10.x, pa11.x);
        s1 = __fadd_rn(pa10.y, pa11.y);
        s2 = __fadd_rn(pa10.z, pa11.z);
        s3 = __fadd_rn(pa10.w, pa11.w);
        mm[lq * 4 + 0][32 + lw] = s0;
        mm[lq * 4 + 1][32 + lw] = s1;
        mm[lq * 4 + 2][32 + lw] = s2;
        mm[lq * 4 + 3][32 + lw] = s3;
        m0 = __fmul_rn(s0, 0.5f); m1 = __fmul_rn(s1, 0.5f);
        m2 = __fmul_rn(s2, 0.5f); m3 = __fmul_rn(s3, 0.5f);
        macc1.x = __fadd_rn(macc1.x, __fmul_rn(m0, m0));
        macc1.y = __fadd_rn(macc1.y, __fmul_rn(m1, m1));
        macc1.z = __fadd_rn(macc1.z, __fmul_rn(m2, m2));
        macc1.w = __fadd_rn(macc1.w, __fmul_rn(m3, m3));
    };

    // B-tile prefetch via cp.async: chunk c -> buffer c & 1.
    // 512 16B-copies per chunk -> 4 per thread, one commit group per chunk.
    auto cp_b = [&](int c) {
        #pragma unroll
        for (int qq = 0; qq < 4; qq++) {
            const int q   = t + qq * NT;     // 0..511
            const int row = q >> 5;          // k within chunk (0..15)
            const int grp = q & 31;          // 4-code group
            const float* src = g_cbT + (size_t)(c * BK + row) * NC + grp * 4;
            uint32_t dst = (uint32_t)__cvta_generic_to_shared(
                &u.mb.c[c & 1][row][grp * 4 + ((grp >> 3) << 2)]);
            asm volatile("cp.async.cg.shared.global [%0], [%1], 16;"
                         :: "r"(dst), "l"(src));
        }
        asm volatile("cp.async.commit_group;" ::: "memory");
    };

    const int bcol = co * 8 + ((co >> 2) << 2);   // gap-padded B base col

    // ---- prologue (R12 order): A0 + B0 in flight, prep slice under latency ----
    do_ldg(0);
    cp_b(0);

    // prep slice (COALESCED): CTA (cg = bid&3, dg = bid>>2) computes partial s
    // over d in [dg*4, dg*4+4) for codes [cg*32, cg*32+32).  Loss-only.
    // 4 warps x 8 codes each; lanes split k (stride-32, 128B-coalesced).
    {
        const int cg = bid & 3, dg = bid >> 2;
        #pragma unroll
        for (int ci = 0; ci < 8; ci++) {
            const int c = cg * 32 + w * 8 + ci;
            const float* crow = cb + (size_t)c * DIM;
            float creg[16];
            #pragma unroll
            for (int j = 0; j < 16; j++) creg[j] = __ldg(&crow[l + 32 * j]);
            float ssum = 0.f;
            #pragma unroll
            for (int dd = 0; dd < 4; dd++) {
                const int d = dg * 4 + dd;
                const float* wrow = W + (size_t)d * DIM;
                float p = 0.f;
                #pragma unroll
                for (int j = 0; j < 16; j++)
                    p = __fmaf_rn(creg[j], __ldg(&wrow[l + 32 * j]), p);
                #pragma unroll
                for (int o = 16; o; o >>= 1)
                    p += __shfl_down_sync(0xffffffffu, p, o);
                if (l == 0) {
                    float diff = p + __ldg(&bias[d]) - __ldg(&crow[d]);
                    ssum = __fadd_rn(ssum, diff * diff);
                }
            }
            if (l == 0) g_s_part[dg][c] = ssum;
        }
    }

    do_store(0);
    do_ldg(1);
    asm volatile("cp.async.wait_group 0;" ::: "memory");
    __syncthreads();

    // ---- pipelined main loop (R12 order): one barrier per chunk ----
    for (int c = 0; c < NCHUNK; c++) {
        if (c + 1 < NCHUNK) {
            do_store((c + 1) & 1);       // ascending chunk order -> chains intact
            cp_b(c + 1);
        }
        if (c + 2 < NCHUNK) do_ldg(c + 2);

        const float (*mm)[BMP]  = u.mb.m[c & 1];
        const float (*cc)[NCP2] = u.mb.c[c & 1];
        #pragma unroll
        for (int k = 0; k < BK; k++) {
            float4 a0 = *(const float4*)&mm[k][wo * 8];
            float4 a1 = *(const float4*)&mm[k][wo * 8 + 4];
            ulonglong2 q0 = *(const ulonglong2*)&cc[k][bcol];
            ulonglong2 q1 = *(const ulonglong2*)&cc[k][bcol + 4];
            const unsigned long long bp0 = q0.x, bp1 = q0.y, bp2 = q1.x, bp3 = q1.y;
            const float av[8] = {a0.x, a0.y, a0.z, a0.w, a1.x, a1.y, a1.z, a1.w};
            #pragma unroll
            for (int i = 0; i < 8; i++) {
                const unsigned long long aa = dup2(av[i]);
                ffma2(acc2[i][0], aa, bp0);
                ffma2(acc2[i][1], aa, bp1);
                ffma2(acc2[i][2], aa, bp2);
                ffma2(acc2[i][3], aa, bp3);
            }
        }
        if (c + 1 < NCHUNK) {
            asm volatile("cp.async.wait_group 0;" ::: "memory");
            __syncthreads();
        }
    }
    __syncthreads();   // all warps done reading tile buffers before epilogue overlay

    // ---- mnorm fold (LLVM order); u.eb.fold aliases the dead tile buffers ----
    u.eb.fold[lw][lq * 4 + 0] = macc0.x;
    u.eb.fold[lw][lq * 4 + 1] = macc0.y;
    u.eb.fold[lw][lq * 4 + 2] = macc0.z;
    u.eb.fold[lw][lq * 4 + 3] = macc0.w;
    u.eb.fold[32 + lw][lq * 4 + 0] = macc1.x;
    u.eb.fold[32 + lw][lq * 4 + 1] = macc1.y;
    u.eb.fold[32 + lw][lq * 4 + 2] = macc1.z;
    u.eb.fold[32 + lw][lq * 4 + 3] = macc1.w;
    __syncthreads();
    if (t < BM) {
        const float* s = u.eb.fold[t];
        float v0 = __fadd_rn(__fadd_rn(__fadd_rn(s[0], s[4]), s[8]),  s[12]);
        float v1 = __fadd_rn(__fadd_rn(__fadd_rn(s[1], s[5]), s[9]),  s[13]);
        float v2 = __fadd_rn(__fadd_rn(__fadd_rn(s[2], s[6]), s[10]), s[14]);
        float v3 = __fadd_rn(__fadd_rn(__fadd_rn(s[3], s[7]), s[11]), s[15]);
        sm_mn[t] = __fadd_rn(__fadd_rn(v0, v1), __fadd_rn(v2, v3));
    }
    __syncthreads();

    // ---- unpack + per-thread argmin, results to smem ----
    float cn[8];
    #pragma unroll
    for (int j = 0; j < 8; j++) cn[j] = __ldg(&g_cnorm[co * 8 + j]);

    #pragma unroll
    for (int i = 0; i < 8; i++) {
        float a[8];
        #pragma unroll
        for (int jp = 0; jp < 4; jp++) {
            float2 v = unpack2(acc2[i][jp]);
            a[2 * jp] = v.x; a[2 * jp + 1] = v.y;
        }
        const float mni = sm_mn[wo * 8 + i];
        float best;
        int bidx = co * 8;
        {
            float tt = __fadd_rn(mni, -a[0]);
            best = __fadd_rn(tt, cn[0]);
        }
        #pragma unroll
        for (int j = 1; j < 8; j++) {
            float tt = __fadd_rn(mni, -a[j]);
            float d2 = __fadd_rn(tt, cn[j]);
            if (d2 < best) { best = d2; bidx = co * 8 + j; }  // strict <: lowest j
        }
        u.eb.bs[wo * 8 + i][co] = best;
        u.eb.bi[wo * 8 + i][co] = bidx;
    }
    __syncthreads();

    // ---- per-word reduction over the 16 co-groups, ascending (first-min) ----
    if (t < BM) {
        float best = u.eb.bs[t][0];
        int   bidx = u.eb.bi[t][0];
        #pragma unroll
        for (int g = 1; g < 16; g++) {
            float s = u.eb.bs[t][g];
            if (s < best) { best = s; bidx = u.eb.bi[t][g]; } // strict <: lowest co
        }
        widx[t] = bidx;
        out_idx[wbase + t] = (float)bidx;
        atomicAdd(&hist[bidx], 1);
    }
    __syncthreads();

    if (t < NC) {
        int h = hist[t];
        if (h) atomicAdd(&g_count[t], h);
    }

    // ---- gather-write word_embeddings (codebook L2-hot, coalesced stores) ----
    for (int f = t; f < BM * (DIM / 4); f += NT) {
        const int wd = f >> 7;
        const int c4 = f & 127;
        const int c  = widx[wd];
        float4 v = *(const float4*)(cb + (size_t)c * DIM + c4 * 4);
        *(float4*)(out_emb + (size_t)(wbase + wd) * DIM + c4 * 4) = v;
    }

    // ---- last-CTA loss: sum_c count[c] * (sum_dg s_part[dg][c]) / (NWORDS*DIM) ----
    __syncthreads();
    if (t == 0) {
        __threadfence();
        unsigned old = atomicAdd(&g_done, 1u);
        is_last = (old == gridDim.x - 1) ? 1 : 0;
    }
    __syncthreads();
    if (is_last) {
        float v = 0.f;
        if (t < NC) {
            __threadfence();
            float s = 0.f;
            #pragma unroll 8
            for (int p = 0; p < NDG; p++)
                s = __fadd_rn(s, g_s_part[p][t]);   // fixed ascending order
            const int cnt = *(volatile int*)&g_count[t];
            v = __fmul_rn((float)cnt, s);
            g_count[t] = 0;                          // reset for next replay
        }
        #pragma unroll
        for (int o = 16; o; o >>= 1) v += __shfl_down_sync(0xffffffffu, v, o);
        if ((t & 31) == 0) sm_ls[t >> 5] = v;
        __syncthreads();
        if (t == 0) {
            float s = __fadd_rn(__fadd_rn(sm_ls[0], sm_ls[1]),
                                __fadd_rn(sm_ls[2], sm_ls[3]));
            out_loss[0] = s * (1.0f / ((float)NWORDS * (float)DIM));
            g_done = 0;
        }
    }
}

// ---------------------------------------------------------------------------
// Inputs (metadata order):
//   d_in[0] char_tokens int32 (unused)  d_in[1] char_embeddings f32 [16,4096,512]
//   d_in[2] word_codebook f32 [128,512] d_in[3] proj_w f32 [512,512]
//   d_in[4] proj_b f32 [512]
// Output (f32, flattened): [0,32768) indices | [.., +32768*512) embeddings | [last] loss
// ---------------------------------------------------------------------------
extern "C" void kernel_launch(void* const* d_in, const int* in_sizes, int n_in,
                              void* d_out, int out_size) {
    const float* emb = (const float*)d_in[1];
    const float* cb  = (const float*)d_in[2];
    const float* W   = (const float*)d_in[3];
    const float* b   = (const float*)d_in[4];
    float* out = (float*)d_out;

    float* out_idx  = out;
    float* out_emb  = out + NWORDS;
    float* out_loss = out + NWORDS + (size_t)NWORDS * DIM;

    cudaFuncSetAttribute(main_kernel,
                         cudaFuncAttributeMaxDynamicSharedMemorySize, DSMEM);

    transpose_kernel<<<NC, 256>>>(cb);
    main_kernel<<<GRID, NT, DSMEM>>>(emb, cb, W, b, out_idx, out_emb, out_loss);
}